// round 12
// baseline (speedup 1.0000x reference)
#include <cuda_runtime.h>

// Problem shape (fixed by the dataset):
//   pred_boxes: [16, 900, 4] fp32 (cxcywh)  -> 14400 preds
//   gt_boxes:   [1600, 4]    fp32 (cxcywh)
//   out:        [16, 900, 1600] fp32 cost = 5*L1 - 2*GIoU
#define MGT    1600
#define COLS4  (MGT / 4)            // 400 float4 columns per pred row
#define NPRED  (16 * 900)           // 14400
#define PPT    4                    // preds per thread
#define NGRP   (NPRED / PPT)        // 3600
#define TOTTH  (NGRP * COLS4)       // 1,440,000 threads
#define TPB    256                  // 5625 blocks, exact

typedef unsigned long long u64;     // packed f32x2 (register pair)

// ---- f32x2 packed helpers ----
__device__ __forceinline__ u64 pk(float lo, float hi) {
    u64 r; asm("mov.b64 %0, {%1, %2};" : "=l"(r) : "f"(lo), "f"(hi)); return r;
}
__device__ __forceinline__ void upk(u64 v, float& lo, float& hi) {
    asm("mov.b64 {%0, %1}, %2;" : "=f"(lo), "=f"(hi) : "l"(v));
}
__device__ __forceinline__ u64 add2(u64 a, u64 b) {
    u64 d; asm("add.rn.f32x2 %0, %1, %2;" : "=l"(d) : "l"(a), "l"(b)); return d;
}
__device__ __forceinline__ u64 mul2(u64 a, u64 b) {
    u64 d; asm("mul.rn.f32x2 %0, %1, %2;" : "=l"(d) : "l"(a), "l"(b)); return d;
}
__device__ __forceinline__ u64 fma2(u64 a, u64 b, u64 c) {
    u64 d; asm("fma.rn.f32x2 %0, %1, %2, %3;" : "=l"(d) : "l"(a), "l"(b), "l"(c)); return d;
}
__device__ __forceinline__ float f_rcp(float a) {                   // MUFU.RCP only
    float d; asm("rcp.approx.f32 %0, %1;" : "=f"(d) : "f"(a)); return d;
}

// GT-derived SoA table: rows = {cx, cy, 0.5*w, 0.5*h, area}
__device__ __align__(16) float g_gt[5][MGT];

__global__ void gt_pre_kernel(const float* __restrict__ gt) {
    int i = blockIdx.x * blockDim.x + threadIdx.x;
    if (i < MGT) {
        float4 b = reinterpret_cast<const float4*>(gt)[i];
        g_gt[0][i] = b.x;
        g_gt[1][i] = b.y;
        g_gt[2][i] = 0.5f * b.z;
        g_gt[3][i] = 0.5f * b.w;
        g_gt[4][i] = b.z * b.w;
    }
}

// Two gt elements (lanes a,b) vs one pred.
// Interval identities (d = center diff, s = half-width sum, dwh = half-width diff):
//   iw_raw = s - max(|d|, |dwh|) ;  ew = s + max(|d|, |dwh|)
//   l1 = |dcx|+|dcy| + 2*(|dwh|+|dhh|)
//   cost = 5*l1 + 2 - 2*(inter/uni + uni/ea)
// Separate reciprocals: rcp(ea) starts before inter/uni exist (shorter
// critical path); tail = iou = inter*rcp(uni); s = uni*rcp(ea) + iou.
__device__ __forceinline__ void cost_pair(
    u64 pcx_p, u64 pcy_p, u64 pwh_p, u64 phh_p, u64 pa_p,
    u64 gcx_p, u64 gcy_p, u64 ghw_p, u64 ghh_p, u64 ga_p,
    u64 cn1, u64 cn2, u64 c5, u64 c2,
    float& ra, float& rb)
{
    // Packed diffs and half-width sums (fma pipe, 6 slots)
    u64 dcx_p = fma2(gcx_p, cn1, pcx_p);
    u64 dcy_p = fma2(gcy_p, cn1, pcy_p);
    u64 dwh_p = fma2(ghw_p, cn1, pwh_p);
    u64 dhh_p = fma2(ghh_p, cn1, phh_p);
    u64 sx_p  = add2(ghw_p, pwh_p);
    u64 sy_p  = add2(ghh_p, phh_p);

    float dcxa, dcxb, dcya, dcyb, dwha, dwhb, dhha, dhhb;
    upk(dcx_p, dcxa, dcxb); upk(dcy_p, dcya, dcyb);
    upk(dwh_p, dwha, dwhb); upk(dhh_p, dhha, dhhb);

    // L1 scalar (|src| folds into FADD): 3 ops/lane
    float l1a = fmaf(2.0f, fabsf(dwha) + fabsf(dhha), fabsf(dcxa) + fabsf(dcya));
    float l1b = fmaf(2.0f, fabsf(dwhb) + fabsf(dhhb), fabsf(dcxb) + fabsf(dcyb));
    u64 l1_p = pk(l1a, l1b);

    // mx = max(|d|,|dwh|) per axis/lane: 4 FMNMX (abs modifiers free)
    u64 mxx_p = pk(fmaxf(fabsf(dcxa), fabsf(dwha)), fmaxf(fabsf(dcxb), fabsf(dwhb)));
    u64 mxy_p = pk(fmaxf(fabsf(dcya), fabsf(dhha)), fmaxf(fabsf(dcyb), fabsf(dhhb)));

    // Enclosing area first -> rcp(ea) overlaps the intersection chain
    u64 ew_p  = add2(mxx_p, sx_p);         // sx + mxx
    u64 eh_p  = add2(mxy_p, sy_p);         // sy + mxy
    u64 ea_p  = mul2(ew_p, eh_p);
    float ea0, ea1; upk(ea_p, ea0, ea1);
    u64 rea_p = pk(f_rcp(ea0), f_rcp(ea1));

    // Raw intersection widths + clamp (4 FMNMX), then packed product
    u64 iwr_p = fma2(mxx_p, cn1, sx_p);    // sx - mxx
    u64 ihr_p = fma2(mxy_p, cn1, sy_p);    // sy - mxy
    float iwra, iwrb, ihra, ihrb;
    upk(iwr_p, iwra, iwrb); upk(ihr_p, ihra, ihrb);
    u64 iw_p = pk(fmaxf(iwra, 0.0f), fmaxf(iwrb, 0.0f));
    u64 ih_p = pk(fmaxf(ihra, 0.0f), fmaxf(ihrb, 0.0f));
    u64 inter_p = mul2(iw_p, ih_p);

    // uni = pa+ga-inter ; iou = inter*rcp(uni) ; s = uni*rcp(ea) + iou
    u64 uni_p = fma2(inter_p, cn1, add2(pa_p, ga_p));
    float u0, u1; upk(uni_p, u0, u1);
    u64 run_p = pk(f_rcp(u0), f_rcp(u1));
    u64 iou_p = mul2(inter_p, run_p);
    u64 s_p   = fma2(uni_p, rea_p, iou_p);

    u64 t_p = fma2(l1_p, c5, c2);          // 5*l1 + 2
    t_p = fma2(s_p, cn2, t_p);             // - 2*s
    upk(t_p, ra, rb);
}

__global__ void __launch_bounds__(TPB, 4)   // 4 CTAs/SM -> <=64 regs
cost_kernel(const float* __restrict__ pred, float* __restrict__ out)
{
    int id = blockIdx.x * TPB + threadIdx.x;
    int pg = id / COLS4;
    int c  = id - pg * COLS4;
    int p0 = pg * PPT;

    const u64 cn1 = pk(-1.0f, -1.0f);
    const u64 cn2 = pk(-2.0f, -2.0f);
    const u64 c5  = pk( 5.0f,  5.0f);
    const u64 c2  = pk( 2.0f,  2.0f);

    // 5 coalesced LDG.128 from the hot GT table
    float4 gcx = reinterpret_cast<const float4*>(g_gt[0])[c];
    float4 gcy = reinterpret_cast<const float4*>(g_gt[1])[c];
    float4 ghw = reinterpret_cast<const float4*>(g_gt[2])[c];
    float4 ghh = reinterpret_cast<const float4*>(g_gt[3])[c];
    float4 ga  = reinterpret_cast<const float4*>(g_gt[4])[c];

    // GT pairs packed once, reused across PPT preds
    u64 gcx01 = pk(gcx.x, gcx.y), gcx23 = pk(gcx.z, gcx.w);
    u64 gcy01 = pk(gcy.x, gcy.y), gcy23 = pk(gcy.z, gcy.w);
    u64 ghw01 = pk(ghw.x, ghw.y), ghw23 = pk(ghw.z, ghw.w);
    u64 ghh01 = pk(ghh.x, ghh.y), ghh23 = pk(ghh.z, ghh.w);
    u64 ga01  = pk(ga.x,  ga.y ), ga23  = pk(ga.z,  ga.w );

    #pragma unroll
    for (int k = 0; k < PPT; ++k) {
        int p = p0 + k;
        // Pred box: identical address across the warp -> broadcast load
        float4 pb = reinterpret_cast<const float4*>(pred)[p];
        float pwh = 0.5f * pb.z;
        float phh = 0.5f * pb.w;
        float pa  = pb.z * pb.w;

        u64 pcx_p = pk(pb.x, pb.x);
        u64 pcy_p = pk(pb.y, pb.y);
        u64 pwh_p = pk(pwh,  pwh);
        u64 phh_p = pk(phh,  phh);
        u64 pa_p  = pk(pa,   pa );

        float4 res;
        cost_pair(pcx_p, pcy_p, pwh_p, phh_p, pa_p,
                  gcx01, gcy01, ghw01, ghh01, ga01,
                  cn1, cn2, c5, c2, res.x, res.y);
        cost_pair(pcx_p, pcy_p, pwh_p, phh_p, pa_p,
                  gcx23, gcy23, ghw23, ghh23, ga23,
                  cn1, cn2, c5, c2, res.z, res.w);

        reinterpret_cast<float4*>(out)[p * COLS4 + c] = res;
    }
}

extern "C" void kernel_launch(void* const* d_in, const int* in_sizes, int n_in,
                              void* d_out, int out_size)
{
    (void)in_sizes; (void)n_in; (void)out_size;
    const float* pred = (const float*)d_in[0];
    const float* gt   = (const float*)d_in[1];
    float* out        = (float*)d_out;

    gt_pre_kernel<<<(MGT + TPB - 1) / TPB, TPB>>>(gt);
    cost_kernel<<<TOTTH / TPB, TPB>>>(pred, out);
}

// round 13
// speedup vs baseline: 1.0811x; 1.0811x over previous
#include <cuda_runtime.h>

// Problem shape (fixed by the dataset):
//   pred_boxes: [16, 900, 4] fp32 (cxcywh)  -> 14400 preds
//   gt_boxes:   [1600, 4]    fp32 (cxcywh)
//   out:        [16, 900, 1600] fp32 cost = 5*L1 - 2*GIoU
#define MGT    1600
#define COLS4  (MGT / 4)            // 400 float4 columns per pred row
#define NPRED  (16 * 900)           // 14400
#define PPT    4                    // preds per thread
#define NGRP   (NPRED / PPT)        // 3600
#define TOTTH  (NGRP * COLS4)       // 1,440,000 threads
#define TPB    256                  // 5625 blocks, exact

typedef unsigned long long u64;     // packed f32x2 (register pair)

// ---- f32x2 packed helpers ----
__device__ __forceinline__ u64 pk(float lo, float hi) {
    u64 r; asm("mov.b64 %0, {%1, %2};" : "=l"(r) : "f"(lo), "f"(hi)); return r;
}
__device__ __forceinline__ void upk(u64 v, float& lo, float& hi) {
    asm("mov.b64 {%0, %1}, %2;" : "=f"(lo), "=f"(hi) : "l"(v));
}
__device__ __forceinline__ u64 add2(u64 a, u64 b) {
    u64 d; asm("add.rn.f32x2 %0, %1, %2;" : "=l"(d) : "l"(a), "l"(b)); return d;
}
__device__ __forceinline__ u64 mul2(u64 a, u64 b) {
    u64 d; asm("mul.rn.f32x2 %0, %1, %2;" : "=l"(d) : "l"(a), "l"(b)); return d;
}
__device__ __forceinline__ u64 fma2(u64 a, u64 b, u64 c) {
    u64 d; asm("fma.rn.f32x2 %0, %1, %2, %3;" : "=l"(d) : "l"(a), "l"(b), "l"(c)); return d;
}
__device__ __forceinline__ float f_rcp(float a) {                   // MUFU.RCP only
    float d; asm("rcp.approx.f32 %0, %1;" : "=f"(d) : "f"(a)); return d;
}

// GT-derived SoA table: rows = {cx, cy, 0.5*w, 0.5*h, area}
__device__ __align__(16) float g_gt[5][MGT];

__global__ void gt_pre_kernel(const float* __restrict__ gt) {
    int i = blockIdx.x * blockDim.x + threadIdx.x;
    if (i < MGT) {
        float4 b = reinterpret_cast<const float4*>(gt)[i];
        g_gt[0][i] = b.x;
        g_gt[1][i] = b.y;
        g_gt[2][i] = 0.5f * b.z;
        g_gt[3][i] = 0.5f * b.w;
        g_gt[4][i] = b.z * b.w;
    }
}

// Two gt elements (lanes a,b) vs one pred.
// Interval identities (d = center diff, s = half-width sum, dwh = half-width diff):
//   iw_raw = s - max(|d|, |dwh|) ;  ew = s + max(|d|, |dwh|)
//   l1 = |dcx|+|dcy| + 2*(|dwh|+|dhh|)
//   cost = 5*l1 + 2 - 2*(inter*ea + uni^2)/(uni*ea)   [combined denominator]
// Epilogue is scalar with FFMA immediates (no packed constant registers).
__device__ __forceinline__ void cost_pair(
    u64 pcx_p, u64 pcy_p, u64 pwh_p, u64 phh_p, u64 pa_p,
    u64 gcx_p, u64 gcy_p, u64 ghw_p, u64 ghh_p, u64 ga_p,
    u64 cn1,
    float& ra, float& rb)
{
    // Packed diffs and half-width sums (fma pipe, 6 slots)
    u64 dcx_p = fma2(gcx_p, cn1, pcx_p);
    u64 dcy_p = fma2(gcy_p, cn1, pcy_p);
    u64 dwh_p = fma2(ghw_p, cn1, pwh_p);
    u64 dhh_p = fma2(ghh_p, cn1, phh_p);
    u64 sx_p  = add2(ghw_p, pwh_p);
    u64 sy_p  = add2(ghh_p, phh_p);

    float dcxa, dcxb, dcya, dcyb, dwha, dwhb, dhha, dhhb;
    upk(dcx_p, dcxa, dcxb); upk(dcy_p, dcya, dcyb);
    upk(dwh_p, dwha, dwhb); upk(dhh_p, dhha, dhhb);

    // L1 scalar (|src| folds into FADD): 3 ops/lane — stays scalar to the end
    float l1a = fmaf(2.0f, fabsf(dwha) + fabsf(dhha), fabsf(dcxa) + fabsf(dcya));
    float l1b = fmaf(2.0f, fabsf(dwhb) + fabsf(dhhb), fabsf(dcxb) + fabsf(dcyb));

    // mx = max(|d|,|dwh|) per axis/lane: 4 FMNMX (abs modifiers free)
    u64 mxx_p = pk(fmaxf(fabsf(dcxa), fabsf(dwha)), fmaxf(fabsf(dcxb), fabsf(dwhb)));
    u64 mxy_p = pk(fmaxf(fabsf(dcya), fabsf(dhha)), fmaxf(fabsf(dcyb), fabsf(dhhb)));

    // Packed: raw intersection widths + enclosing widths
    u64 iwr_p = fma2(mxx_p, cn1, sx_p);    // sx - mxx
    u64 ihr_p = fma2(mxy_p, cn1, sy_p);    // sy - mxy
    u64 ew_p  = add2(mxx_p, sx_p);         // sx + mxx
    u64 eh_p  = add2(mxy_p, sy_p);         // sy + mxy
    u64 ea_p  = mul2(ew_p, eh_p);

    // Clamp scalar (4 FMNMX), then packed products
    float iwra, iwrb, ihra, ihrb;
    upk(iwr_p, iwra, iwrb); upk(ihr_p, ihra, ihrb);
    u64 iw_p = pk(fmaxf(iwra, 0.0f), fmaxf(iwrb, 0.0f));
    u64 ih_p = pk(fmaxf(ihra, 0.0f), fmaxf(ihrb, 0.0f));
    u64 inter_p = mul2(iw_p, ih_p);

    // Packed GIoU tail with combined denominator (1 MUFU per element)
    u64 uni_p = fma2(inter_p, cn1, add2(pa_p, ga_p));     // pa+ga-inter
    u64 m_p   = mul2(uni_p, ea_p);                        // uni*ea
    float m0, m1; upk(m_p, m0, m1);
    u64 r_p  = pk(f_rcp(m0), f_rcp(m1));                  // 2x MUFU.RCP
    u64 nb_p = fma2(uni_p, uni_p, mul2(inter_p, ea_p));   // inter*ea + uni^2
    u64 s_p  = mul2(nb_p, r_p);                           // iou + uni/ea

    // Scalar epilogue with FFMA immediates — no packed constant regs
    float s0, s1; upk(s_p, s0, s1);
    ra = fmaf(-2.0f, s0, fmaf(5.0f, l1a, 2.0f));
    rb = fmaf(-2.0f, s1, fmaf(5.0f, l1b, 2.0f));
}

__global__ void __launch_bounds__(TPB, 5)   // 5 CTAs/SM -> <=48 regs (reg diet)
cost_kernel(const float* __restrict__ pred, float* __restrict__ out)
{
    int id = blockIdx.x * TPB + threadIdx.x;
    int pg = id / COLS4;
    int c  = id - pg * COLS4;
    int p0 = pg * PPT;

    const u64 cn1 = pk(-1.0f, -1.0f);

    // 5 coalesced LDG.128 from the hot GT table
    float4 gcx = reinterpret_cast<const float4*>(g_gt[0])[c];
    float4 gcy = reinterpret_cast<const float4*>(g_gt[1])[c];
    float4 ghw = reinterpret_cast<const float4*>(g_gt[2])[c];
    float4 ghh = reinterpret_cast<const float4*>(g_gt[3])[c];
    float4 ga  = reinterpret_cast<const float4*>(g_gt[4])[c];

    // GT pairs packed once, reused across PPT preds (adjacent float4 lanes
    // -> aligned register pairs, pk is a rename)
    u64 gcx01 = pk(gcx.x, gcx.y), gcx23 = pk(gcx.z, gcx.w);
    u64 gcy01 = pk(gcy.x, gcy.y), gcy23 = pk(gcy.z, gcy.w);
    u64 ghw01 = pk(ghw.x, ghw.y), ghw23 = pk(ghw.z, ghw.w);
    u64 ghh01 = pk(ghh.x, ghh.y), ghh23 = pk(ghh.z, ghh.w);
    u64 ga01  = pk(ga.x,  ga.y ), ga23  = pk(ga.z,  ga.w );

    #pragma unroll
    for (int k = 0; k < PPT; ++k) {
        int p = p0 + k;
        // Pred box: identical address across the warp -> broadcast load
        float4 pb = reinterpret_cast<const float4*>(pred)[p];
        float pwh = 0.5f * pb.z;
        float phh = 0.5f * pb.w;
        float pa  = pb.z * pb.w;

        u64 pcx_p = pk(pb.x, pb.x);
        u64 pcy_p = pk(pb.y, pb.y);
        u64 pwh_p = pk(pwh,  pwh);
        u64 phh_p = pk(phh,  phh);
        u64 pa_p  = pk(pa,   pa );

        float4 res;
        cost_pair(pcx_p, pcy_p, pwh_p, phh_p, pa_p,
                  gcx01, gcy01, ghw01, ghh01, ga01,
                  cn1, res.x, res.y);
        cost_pair(pcx_p, pcy_p, pwh_p, phh_p, pa_p,
                  gcx23, gcy23, ghw23, ghh23, ga23,
                  cn1, res.z, res.w);

        reinterpret_cast<float4*>(out)[p * COLS4 + c] = res;
    }
}

extern "C" void kernel_launch(void* const* d_in, const int* in_sizes, int n_in,
                              void* d_out, int out_size)
{
    (void)in_sizes; (void)n_in; (void)out_size;
    const float* pred = (const float*)d_in[0];
    const float* gt   = (const float*)d_in[1];
    float* out        = (float*)d_out;

    gt_pre_kernel<<<(MGT + TPB - 1) / TPB, TPB>>>(gt);
    cost_kernel<<<TOTTH / TPB, TPB>>>(pred, out);
}

// round 14
// speedup vs baseline: 1.0853x; 1.0039x over previous
#include <cuda_runtime.h>

// Problem shape (fixed by the dataset):
//   pred_boxes: [16, 900, 4] fp32 (cxcywh)  -> 14400 preds
//   gt_boxes:   [1600, 4]    fp32 (cxcywh)
//   out:        [16, 900, 1600] fp32 cost = 5*L1 - 2*GIoU
#define MGT    1600
#define COLS4  (MGT / 4)            // 400 float4 columns per pred row
#define NPRED  (16 * 900)           // 14400
#define PPT    4                    // preds per thread
#define NGRP   (NPRED / PPT)        // 3600
#define TOTTH  (NGRP * COLS4)       // 1,440,000 threads
#define TPB    256                  // 5625 blocks, exact

typedef unsigned long long u64;     // packed f32x2 (register pair)

// ---- f32x2 packed helpers ----
__device__ __forceinline__ u64 pk(float lo, float hi) {
    u64 r; asm("mov.b64 %0, {%1, %2};" : "=l"(r) : "f"(lo), "f"(hi)); return r;
}
__device__ __forceinline__ void upk(u64 v, float& lo, float& hi) {
    asm("mov.b64 {%0, %1}, %2;" : "=f"(lo), "=f"(hi) : "l"(v));
}
__device__ __forceinline__ u64 add2(u64 a, u64 b) {
    u64 d; asm("add.rn.f32x2 %0, %1, %2;" : "=l"(d) : "l"(a), "l"(b)); return d;
}
__device__ __forceinline__ u64 mul2(u64 a, u64 b) {
    u64 d; asm("mul.rn.f32x2 %0, %1, %2;" : "=l"(d) : "l"(a), "l"(b)); return d;
}
__device__ __forceinline__ u64 fma2(u64 a, u64 b, u64 c) {
    u64 d; asm("fma.rn.f32x2 %0, %1, %2, %3;" : "=l"(d) : "l"(a), "l"(b), "l"(c)); return d;
}
__device__ __forceinline__ float f_rcp(float a) {                   // MUFU.RCP only
    float d; asm("rcp.approx.f32 %0, %1;" : "=f"(d) : "f"(a)); return d;
}

// GT-derived SoA table: rows = {cx, cy, 0.5*w, 0.5*h, area}
__device__ __align__(16) float g_gt[5][MGT];

__global__ void gt_pre_kernel(const float* __restrict__ gt) {
    int i = blockIdx.x * blockDim.x + threadIdx.x;
    if (i < MGT) {
        float4 b = reinterpret_cast<const float4*>(gt)[i];
        g_gt[0][i] = b.x;
        g_gt[1][i] = b.y;
        g_gt[2][i] = 0.5f * b.z;
        g_gt[3][i] = 0.5f * b.w;
        g_gt[4][i] = b.z * b.w;
    }
}

// Two gt elements (lanes a,b) vs one pred.
// Interval identities (d = center diff, s = half-width sum, dwh = half-width diff):
//   iw_raw = s - max(|d|, |dwh|) ;  ew = s + max(|d|, |dwh|)
//   l1 = |dcx|+|dcy| + 2*(|dwh|+|dhh|)
//   cost = 5*l1 + 2 - 2*(inter*ea + uni^2)/(uni*ea)   [combined denominator]
__device__ __forceinline__ void cost_pair(
    u64 pcx_p, u64 pcy_p, u64 pwh_p, u64 phh_p, u64 pa_p,
    u64 gcx_p, u64 gcy_p, u64 ghw_p, u64 ghh_p, u64 ga_p,
    u64 cn1,
    float& ra, float& rb)
{
    // Packed diffs and half-width sums (fma pipe, 6 slots)
    u64 dcx_p = fma2(gcx_p, cn1, pcx_p);
    u64 dcy_p = fma2(gcy_p, cn1, pcy_p);
    u64 dwh_p = fma2(ghw_p, cn1, pwh_p);
    u64 dhh_p = fma2(ghh_p, cn1, phh_p);
    u64 sx_p  = add2(ghw_p, pwh_p);
    u64 sy_p  = add2(ghh_p, phh_p);

    float dcxa, dcxb, dcya, dcyb, dwha, dwhb, dhha, dhhb;
    upk(dcx_p, dcxa, dcxb); upk(dcy_p, dcya, dcyb);
    upk(dwh_p, dwha, dwhb); upk(dhh_p, dhha, dhhb);

    // L1 scalar (|src| folds into FADD): 3 ops/lane
    float l1a = fmaf(2.0f, fabsf(dwha) + fabsf(dhha), fabsf(dcxa) + fabsf(dcya));
    float l1b = fmaf(2.0f, fabsf(dwhb) + fabsf(dhhb), fabsf(dcxb) + fabsf(dcyb));

    // mx = max(|d|,|dwh|) per axis/lane: 4 FMNMX (abs modifiers free)
    u64 mxx_p = pk(fmaxf(fabsf(dcxa), fabsf(dwha)), fmaxf(fabsf(dcxb), fabsf(dwhb)));
    u64 mxy_p = pk(fmaxf(fabsf(dcya), fabsf(dhha)), fmaxf(fabsf(dcyb), fabsf(dhhb)));

    // Packed: raw intersection widths + enclosing widths
    u64 iwr_p = fma2(mxx_p, cn1, sx_p);    // sx - mxx
    u64 ihr_p = fma2(mxy_p, cn1, sy_p);    // sy - mxy
    u64 ew_p  = add2(mxx_p, sx_p);         // sx + mxx
    u64 eh_p  = add2(mxy_p, sy_p);         // sy + mxy
    u64 ea_p  = mul2(ew_p, eh_p);

    // Clamp scalar (4 FMNMX), then packed products
    float iwra, iwrb, ihra, ihrb;
    upk(iwr_p, iwra, iwrb); upk(ihr_p, ihra, ihrb);
    u64 iw_p = pk(fmaxf(iwra, 0.0f), fmaxf(iwrb, 0.0f));
    u64 ih_p = pk(fmaxf(ihra, 0.0f), fmaxf(ihrb, 0.0f));
    u64 inter_p = mul2(iw_p, ih_p);

    // Packed GIoU tail with combined denominator
    u64 uni_p = fma2(inter_p, cn1, add2(pa_p, ga_p));     // pa+ga-inter
    u64 m_p   = mul2(uni_p, ea_p);                        // uni*ea
    float m0, m1; upk(m_p, m0, m1);
    u64 r_p  = pk(f_rcp(m0), f_rcp(m1));                  // 2x MUFU.RCP
    u64 nb_p = fma2(uni_p, uni_p, mul2(inter_p, ea_p));   // inter*ea + uni^2
    u64 s_p  = mul2(nb_p, r_p);                           // iou + uni/ea

    // Scalar epilogue with FFMA immediates — no packed constant regs
    float s0, s1; upk(s_p, s0, s1);
    ra = fmaf(-2.0f, s0, fmaf(5.0f, l1a, 2.0f));
    rb = fmaf(-2.0f, s1, fmaf(5.0f, l1b, 2.0f));
}

__global__ void __launch_bounds__(TPB, 5)   // 5 CTAs/SM -> <=48 regs
cost_kernel(const float* __restrict__ pred, float* __restrict__ out)
{
    int id = blockIdx.x * TPB + threadIdx.x;
    int pg = id / COLS4;
    int c  = id - pg * COLS4;
    int p0 = pg * PPT;

    const u64 cn1 = pk(-1.0f, -1.0f);

    // PDL: block is scheduled during gt_pre_kernel's launch/exec window;
    // wait here (after index math) until g_gt writes are visible.
    cudaGridDependencySynchronize();

    // 5 coalesced LDG.128 from the hot GT table
    float4 gcx = reinterpret_cast<const float4*>(g_gt[0])[c];
    float4 gcy = reinterpret_cast<const float4*>(g_gt[1])[c];
    float4 ghw = reinterpret_cast<const float4*>(g_gt[2])[c];
    float4 ghh = reinterpret_cast<const float4*>(g_gt[3])[c];
    float4 ga  = reinterpret_cast<const float4*>(g_gt[4])[c];

    // GT pairs packed once, reused across PPT preds
    u64 gcx01 = pk(gcx.x, gcx.y), gcx23 = pk(gcx.z, gcx.w);
    u64 gcy01 = pk(gcy.x, gcy.y), gcy23 = pk(gcy.z, gcy.w);
    u64 ghw01 = pk(ghw.x, ghw.y), ghw23 = pk(ghw.z, ghw.w);
    u64 ghh01 = pk(ghh.x, ghh.y), ghh23 = pk(ghh.z, ghh.w);
    u64 ga01  = pk(ga.x,  ga.y ), ga23  = pk(ga.z,  ga.w );

    #pragma unroll
    for (int k = 0; k < PPT; ++k) {
        int p = p0 + k;
        // Pred box: identical address across the warp -> broadcast load
        float4 pb = reinterpret_cast<const float4*>(pred)[p];
        float pwh = 0.5f * pb.z;
        float phh = 0.5f * pb.w;
        float pa  = pb.z * pb.w;

        u64 pcx_p = pk(pb.x, pb.x);
        u64 pcy_p = pk(pb.y, pb.y);
        u64 pwh_p = pk(pwh,  pwh);
        u64 phh_p = pk(phh,  phh);
        u64 pa_p  = pk(pa,   pa );

        float4 res;
        cost_pair(pcx_p, pcy_p, pwh_p, phh_p, pa_p,
                  gcx01, gcy01, ghw01, ghh01, ga01,
                  cn1, res.x, res.y);
        cost_pair(pcx_p, pcy_p, pwh_p, phh_p, pa_p,
                  gcx23, gcy23, ghw23, ghh23, ga23,
                  cn1, res.z, res.w);

        reinterpret_cast<float4*>(out)[p * COLS4 + c] = res;
    }
}

extern "C" void kernel_launch(void* const* d_in, const int* in_sizes, int n_in,
                              void* d_out, int out_size)
{
    (void)in_sizes; (void)n_in; (void)out_size;
    const float* pred = (const float*)d_in[0];
    const float* gt   = (const float*)d_in[1];
    float* out        = (float*)d_out;

    gt_pre_kernel<<<(MGT + TPB - 1) / TPB, TPB>>>(gt);

    // Programmatic dependent launch: cost_kernel may begin scheduling while
    // gt_pre_kernel runs; correctness enforced by cudaGridDependencySynchronize.
    cudaLaunchConfig_t cfg = {};
    cfg.gridDim  = dim3(TOTTH / TPB);
    cfg.blockDim = dim3(TPB);
    cfg.dynamicSmemBytes = 0;
    cfg.stream = 0;
    cudaLaunchAttribute attr[1];
    attr[0].id = cudaLaunchAttributeProgrammaticStreamSerialization;
    attr[0].val.programmaticStreamSerializationAllowed = 1;
    cfg.attrs = attr;
    cfg.numAttrs = 1;
    cudaLaunchKernelEx(&cfg, cost_kernel, pred, out);
}